// round 8
// baseline (speedup 1.0000x reference)
#include <cuda_runtime.h>
#include <math.h>

#define BATCH 16
#define NP 6
#define NPTS 262144
#define BPB 64                          // blocks per batch element
#define NBLOCKS (BATCH*BPB)             // 1024
#define TPB 256
#define PTS_PER_BLOCK (NPTS/BPB)        // 4096
#define V4_PER_BLOCK (PTS_PER_BLOCK/4)  // 1024
#define NITER (V4_PER_BLOCK/TPB)        // 4

typedef unsigned long long u64;

// ---- packed f32x2 helpers (sm_103a) ---------------------------------------
__device__ __forceinline__ u64 pk2(float lo, float hi) {
    u64 r; asm("mov.b64 %0,{%1,%2};" : "=l"(r) : "f"(lo), "f"(hi)); return r;
}
__device__ __forceinline__ void up2(u64 v, float& lo, float& hi) {
    asm("mov.b64 {%0,%1},%2;" : "=f"(lo), "=f"(hi) : "l"(v));
}
__device__ __forceinline__ u64 fma2_(u64 a, u64 b, u64 c) {
    u64 r; asm("fma.rn.f32x2 %0,%1,%2,%3;" : "=l"(r) : "l"(a), "l"(b), "l"(c)); return r;
}
__device__ __forceinline__ u64 mul2_(u64 a, u64 b) {
    u64 r; asm("mul.rn.f32x2 %0,%1,%2;" : "=l"(r) : "l"(a), "l"(b)); return r;
}
__device__ __forceinline__ u64 add2_(u64 a, u64 b) {
    u64 r; asm("add.rn.f32x2 %0,%1,%2;" : "=l"(r) : "l"(a), "l"(b)); return r;
}
__device__ __forceinline__ float sqrt_approx(float x) {
    float s; asm("sqrt.approx.f32 %0,%1;" : "=f"(s) : "f"(x)); return s;
}

// Scratch (device globals — no allocation allowed)
__device__ float g_partial[NBLOCKS*NP];

// gamma^(P-1-p) for p=0..5, gamma=0.8
__device__ __constant__ float W_GAMMA[NP] =
    {0.32768f, 0.4096f, 0.512f, 0.64f, 0.8f, 1.0f};

// q_rel = conj(q_p) (x) q_t for (p,b).
__device__ __forceinline__ void qrel(const float* __restrict__ tq,
                                     const float* __restrict__ rq,
                                     int p, int b,
                                     float& w, float& x, float& y, float& z)
{
    float t0 = tq[b*4+0], t1 = tq[b*4+1], t2 = tq[b*4+2], t3 = tq[b*4+3];
    float rn = rsqrtf(t0*t0 + t1*t1 + t2*t2 + t3*t3);
    t0 *= rn; t1 *= rn; t2 *= rn; t3 *= rn;

    const float* q = rq + (size_t)(p*BATCH + b)*4;
    float a0 = q[0], a1 = q[1], a2 = q[2], a3 = q[3];
    rn = rsqrtf(a0*a0 + a1*a1 + a2*a2 + a3*a3);
    a0 *= rn; a1 = -a1*rn; a2 = -a2*rn; a3 = -a3*rn;   // conj, normalized

    w = a0*t0 - a1*t1 - a2*t2 - a3*t3;
    x = a0*t1 + a1*t0 + a2*t3 - a3*t2;
    y = a0*t2 - a1*t3 + a2*t0 + a3*t1;
    z = a0*t3 + a1*t2 - a2*t1 + a3*t0;
}

// ---------------------------------------------------------------------------
// Main kernel: R2 mainloop (f32x2 + XOR negation) + double-buffered loads,
// register budget pinned to keep 3 CTAs/SM.
// ---------------------------------------------------------------------------
__global__ __launch_bounds__(TPB, 3)
void pc_kernel(const float* __restrict__ pc,
               const float* __restrict__ tq,
               const float* __restrict__ rq)
{
    int blk   = blockIdx.x;
    int b     = blk >> 6;               // / BPB
    int chunk = blk & (BPB - 1);

    __shared__ float s_ux[NP], s_uy[NP], s_uz[NP], s_c[NP];

    if (threadIdx.x < NP) {
        int p = threadIdx.x;
        float w, x, y, z;
        qrel(tq, rq, p, b, w, x, y, z);
        float vn = sqrtf(x*x + y*y + z*z);
        if (vn > 1e-20f) {
            float inv = 1.0f / vn;
            s_ux[p] = x*inv; s_uy[p] = y*inv; s_uz[p] = z*inv;
            s_c[p]  = 2.0f * vn;
        } else {
            s_ux[p] = 1.0f; s_uy[p] = 0.0f; s_uz[p] = 0.0f; s_c[p] = 0.0f;
        }
    }
    __syncthreads();

    u64 ux2[NP], uy2[NP], uz2[NP];
#pragma unroll
    for (int p = 0; p < NP; ++p) {
        ux2[p] = pk2(s_ux[p], s_ux[p]);
        uy2[p] = pk2(s_uy[p], s_uy[p]);
        uz2[p] = pk2(s_uz[p], s_uz[p]);
    }

    const size_t base = (size_t)b * 4 * NPTS + (size_t)chunk * PTS_PER_BLOCK;
    const float4* xr = (const float4*)(pc + base);
    const float4* yr = (const float4*)(pc + base + NPTS);
    const float4* zr = (const float4*)(pc + base + 2*NPTS);

    u64 acc2[NP];
#pragma unroll
    for (int p = 0; p < NP; ++p) acc2[p] = 0ull;

    const u64 SGN = 0x8000000080000000ULL;

    // double-buffered loads: 6 LDG.128 in flight
    int i0 = threadIdx.x;
    float4 X = xr[i0], Y = yr[i0], Z = zr[i0];

#pragma unroll
    for (int it = 0; it < NITER; ++it) {
        float4 Xc = X, Yc = Y, Zc = Z;
        if (it + 1 < NITER) {
            int i1 = i0 + TPB;
            X = xr[i1]; Y = yr[i1]; Z = zr[i1];
            i0 = i1;
        }
#pragma unroll
        for (int j = 0; j < 2; ++j) {
            u64 x = (j == 0) ? pk2(Xc.x, Xc.y) : pk2(Xc.z, Xc.w);
            u64 y = (j == 0) ? pk2(Yc.x, Yc.y) : pk2(Yc.z, Yc.w);
            u64 z = (j == 0) ? pk2(Zc.x, Zc.y) : pk2(Zc.z, Zc.w);
            u64 r2 = fma2_(x, x, fma2_(y, y, mul2_(z, z)));
#pragma unroll
            for (int p = 0; p < NP; ++p) {
                u64 d  = fma2_(ux2[p], x, fma2_(uy2[p], y, mul2_(uz2[p], z)));
                u64 nd = d ^ SGN;                    // ALU pipe (idle)
                u64 t  = fma2_(nd, d, r2);           // r2 - d^2
                float t0, t1; up2(t, t0, t1);
                float s0 = sqrt_approx(fmaxf(t0, 0.0f));
                float s1 = sqrt_approx(fmaxf(t1, 0.0f));
                acc2[p] = add2_(acc2[p], pk2(s0, s1));
            }
        }
    }

    // collapse packed halves, warp reduce, cross-warp via shared
    float acc[NP];
#pragma unroll
    for (int p = 0; p < NP; ++p) {
        float lo, hi; up2(acc2[p], lo, hi);
        acc[p] = lo + hi;
#pragma unroll
        for (int off = 16; off > 0; off >>= 1)
            acc[p] += __shfl_down_sync(0xffffffffu, acc[p], off);
    }

    __shared__ float sh[TPB/32][NP];
    int warp = threadIdx.x >> 5, lane = threadIdx.x & 31;
    if (lane == 0) {
#pragma unroll
        for (int p = 0; p < NP; ++p) sh[warp][p] = acc[p];
    }
    __syncthreads();
    if (threadIdx.x < NP) {
        int p = threadIdx.x;
        float s = 0.0f;
#pragma unroll
        for (int wi = 0; wi < TPB/32; ++wi) s += sh[wi][p];
        g_partial[blk*NP + p] = s * s_c[p];
    }
}

// ---------------------------------------------------------------------------
// Final: 384 threads; 4-way split of the 64-partial sums (L2 resident).
// ---------------------------------------------------------------------------
__global__ void final_kernel(const float* __restrict__ tq,
                             const float* __restrict__ rq,
                             float* __restrict__ out)
{
    __shared__ float sh4[NP*BATCH][4];
    __shared__ float s_pcl[NP*BATCH];
    __shared__ float s_rot[NP*BATCH];
    int t = threadIdx.x;

    if (t < 4*NP*BATCH) {                 // 384 threads
        int g = t >> 2, k = t & 3;
        int p = g / BATCH, bb = g % BATCH;
        float s = 0.0f;
#pragma unroll
        for (int j = 0; j < BPB/4; ++j)   // 16 each
            s += __ldcg(&g_partial[((size_t)bb*BPB + k*(BPB/4) + j)*NP + p]);
        sh4[g][k] = s;
    }
    __syncthreads();

    if (t < NP*BATCH) {
        int p = t / BATCH, bb = t % BATCH;
        s_pcl[t] = (sh4[t][0] + sh4[t][1] + sh4[t][2] + sh4[t][3])
                   * (1.0f / (float)NPTS);
        float w, x, y, z;
        qrel(tq, rq, p, bb, w, x, y, z);
        s_rot[t] = 2.0f * atan2f(sqrtf(x*x + y*y + z*z), fabsf(w));
    }
    __syncthreads();

    if (t == 0) {
        float total = 0.0f, rl = 0.0f, pl = 0.0f;
#pragma unroll
        for (int p = 0; p < NP; ++p) {
            float pcl = 0.0f, rot = 0.0f;
#pragma unroll
            for (int bb = 0; bb < BATCH; ++bb) {
                pcl += s_pcl[p*BATCH + bb];
                rot += s_rot[p*BATCH + bb];
            }
            rot *= (1.0f / (float)BATCH);
            float pclB = pcl * (1.0f / (float)BATCH);
            float wgt = W_GAMMA[p];
            total += wgt * (0.5f * rot + 0.5f * pclB);
            rl    += wgt * rot;
            pl    += wgt * pclB;
        }
        out[0] = total; out[1] = rl; out[2] = pl;
    }
}

extern "C" void kernel_launch(void* const* d_in, const int* in_sizes, int n_in,
                              void* d_out, int out_size)
{
    (void)in_sizes; (void)n_in; (void)out_size;
    const float* pc = (const float*)d_in[0];   // point_clouds [B,4,N]
    // d_in[1] = target_transl (cancels analytically — unused)
    const float* tr = (const float*)d_in[2];   // target_rot [B,4]
    const float* rl = (const float*)d_in[3];   // rot_list [P,B,4]

    pc_kernel   <<<NBLOCKS, TPB>>>(pc, tr, rl);
    final_kernel<<<1, 384>>>(tr, rl, (float*)d_out);
}

// round 9
// speedup vs baseline: 1.0244x; 1.0244x over previous
#include <cuda_runtime.h>
#include <math.h>
#include <stdint.h>

#define BATCH 16
#define NP 6
#define NPTS 262144
#define BPB 64                          // blocks per batch element
#define NBLOCKS (BATCH*BPB)             // 1024
#define TPB 256
#define PTS_PER_BLOCK (NPTS/BPB)        // 4096
#define V4_PER_BLOCK (PTS_PER_BLOCK/4)  // 1024
#define NITER (V4_PER_BLOCK/TPB)        // 4

typedef unsigned long long u64;

// ---- packed f32x2 helpers (sm_103a) ---------------------------------------
__device__ __forceinline__ u64 pk2(float lo, float hi) {
    u64 r; asm("mov.b64 %0,{%1,%2};" : "=l"(r) : "f"(lo), "f"(hi)); return r;
}
__device__ __forceinline__ void up2(u64 v, float& lo, float& hi) {
    asm("mov.b64 {%0,%1},%2;" : "=f"(lo), "=f"(hi) : "l"(v));
}
__device__ __forceinline__ u64 fma2_(u64 a, u64 b, u64 c) {
    u64 r; asm("fma.rn.f32x2 %0,%1,%2,%3;" : "=l"(r) : "l"(a), "l"(b), "l"(c)); return r;
}
__device__ __forceinline__ u64 mul2_(u64 a, u64 b) {
    u64 r; asm("mul.rn.f32x2 %0,%1,%2;" : "=l"(r) : "l"(a), "l"(b)); return r;
}
__device__ __forceinline__ u64 add2_(u64 a, u64 b) {
    u64 r; asm("add.rn.f32x2 %0,%1,%2;" : "=l"(r) : "l"(a), "l"(b)); return r;
}
__device__ __forceinline__ float sqrt_approx(float x) {
    float s; asm("sqrt.approx.f32 %0,%1;" : "=f"(s) : "f"(x)); return s;
}

// ---- cp.async helpers -------------------------------------------------------
__device__ __forceinline__ void cpasync16(uint32_t smem_dst, const void* gptr) {
    asm volatile("cp.async.cg.shared.global [%0], [%1], 16;"
                 :: "r"(smem_dst), "l"(gptr));
}
__device__ __forceinline__ void cp_commit() {
    asm volatile("cp.async.commit_group;");
}
template<int N> __device__ __forceinline__ void cp_wait() {
    asm volatile("cp.async.wait_group %0;" :: "n"(N));
}

// Scratch (device globals — no allocation allowed)
__device__ float g_partial[NBLOCKS*NP];

// gamma^(P-1-p) for p=0..5, gamma=0.8
__device__ __constant__ float W_GAMMA[NP] =
    {0.32768f, 0.4096f, 0.512f, 0.64f, 0.8f, 1.0f};

// q_rel = conj(q_p) (x) q_t for (p,b).
__device__ __forceinline__ void qrel(const float* __restrict__ tq,
                                     const float* __restrict__ rq,
                                     int p, int b,
                                     float& w, float& x, float& y, float& z)
{
    float t0 = tq[b*4+0], t1 = tq[b*4+1], t2 = tq[b*4+2], t3 = tq[b*4+3];
    float rn = rsqrtf(t0*t0 + t1*t1 + t2*t2 + t3*t3);
    t0 *= rn; t1 *= rn; t2 *= rn; t3 *= rn;

    const float* q = rq + (size_t)(p*BATCH + b)*4;
    float a0 = q[0], a1 = q[1], a2 = q[2], a3 = q[3];
    rn = rsqrtf(a0*a0 + a1*a1 + a2*a2 + a3*a3);
    a0 *= rn; a1 = -a1*rn; a2 = -a2*rn; a3 = -a3*rn;   // conj, normalized

    w = a0*t0 - a1*t1 - a2*t2 - a3*t3;
    x = a0*t1 + a1*t0 + a2*t3 - a3*t2;
    y = a0*t2 - a1*t3 + a2*t0 + a3*t1;
    z = a0*t3 + a1*t2 - a2*t1 + a3*t0;
}

// ---------------------------------------------------------------------------
// Main kernel: cp.async double-buffered smem pipeline + f32x2/XOR mainloop.
// ---------------------------------------------------------------------------
__global__ __launch_bounds__(TPB)
void pc_kernel(const float* __restrict__ pc,
               const float* __restrict__ tq,
               const float* __restrict__ rq)
{
    int blk   = blockIdx.x;
    int b     = blk >> 6;               // / BPB
    int chunk = blk & (BPB - 1);
    int tid   = threadIdx.x;

    __shared__ float s_ux[NP], s_uy[NP], s_uz[NP], s_c[NP];
    __shared__ float4 s_buf[2][3][TPB];   // [stage][stream][thread] = 24 KB

    if (tid < NP) {
        int p = tid;
        float w, x, y, z;
        qrel(tq, rq, p, b, w, x, y, z);
        float vn = sqrtf(x*x + y*y + z*z);
        if (vn > 1e-20f) {
            float inv = 1.0f / vn;
            s_ux[p] = x*inv; s_uy[p] = y*inv; s_uz[p] = z*inv;
            s_c[p]  = 2.0f * vn;
        } else {
            s_ux[p] = 1.0f; s_uy[p] = 0.0f; s_uz[p] = 0.0f; s_c[p] = 0.0f;
        }
    }

    const size_t base = (size_t)b * 4 * NPTS + (size_t)chunk * PTS_PER_BLOCK;
    const float4* xr = (const float4*)(pc + base);
    const float4* yr = (const float4*)(pc + base + NPTS);
    const float4* zr = (const float4*)(pc + base + 2*NPTS);

    uint32_t sb = (uint32_t)__cvta_generic_to_shared(&s_buf[0][0][0]);

    // issue stage 0
    {
        int i = tid;
        cpasync16(sb + (uint32_t)(((0*3 + 0)*TPB + tid)*16), xr + i);
        cpasync16(sb + (uint32_t)(((0*3 + 1)*TPB + tid)*16), yr + i);
        cpasync16(sb + (uint32_t)(((0*3 + 2)*TPB + tid)*16), zr + i);
        cp_commit();
    }
    __syncthreads();   // also covers s_ux..s_c init

    u64 ux2[NP], uy2[NP], uz2[NP];
#pragma unroll
    for (int p = 0; p < NP; ++p) {
        ux2[p] = pk2(s_ux[p], s_ux[p]);
        uy2[p] = pk2(s_uy[p], s_uy[p]);
        uz2[p] = pk2(s_uz[p], s_uz[p]);
    }

    u64 acc2[NP];
#pragma unroll
    for (int p = 0; p < NP; ++p) acc2[p] = 0ull;

    const u64 SGN = 0x8000000080000000ULL;

#pragma unroll
    for (int it = 0; it < NITER; ++it) {
        // issue next stage before consuming current
        if (it + 1 < NITER) {
            int s1 = (it + 1) & 1;
            int i  = (it + 1) * TPB + tid;
            cpasync16(sb + (uint32_t)(((s1*3 + 0)*TPB + tid)*16), xr + i);
            cpasync16(sb + (uint32_t)(((s1*3 + 1)*TPB + tid)*16), yr + i);
            cpasync16(sb + (uint32_t)(((s1*3 + 2)*TPB + tid)*16), zr + i);
            cp_commit();
            cp_wait<1>();          // current stage complete
        } else {
            cp_wait<0>();
        }
        __syncthreads();

        int s = it & 1;
        float4 X = s_buf[s][0][tid];
        float4 Y = s_buf[s][1][tid];
        float4 Z = s_buf[s][2][tid];

#pragma unroll
        for (int j = 0; j < 2; ++j) {
            u64 x = (j == 0) ? pk2(X.x, X.y) : pk2(X.z, X.w);
            u64 y = (j == 0) ? pk2(Y.x, Y.y) : pk2(Y.z, Y.w);
            u64 z = (j == 0) ? pk2(Z.x, Z.y) : pk2(Z.z, Z.w);
            u64 r2 = fma2_(x, x, fma2_(y, y, mul2_(z, z)));
#pragma unroll
            for (int p = 0; p < NP; ++p) {
                u64 d  = fma2_(ux2[p], x, fma2_(uy2[p], y, mul2_(uz2[p], z)));
                u64 nd = d ^ SGN;                    // ALU pipe (idle)
                u64 t  = fma2_(nd, d, r2);           // r2 - d^2
                float t0, t1; up2(t, t0, t1);
                float s0 = sqrt_approx(fmaxf(t0, 0.0f));
                float s1 = sqrt_approx(fmaxf(t1, 0.0f));
                acc2[p] = add2_(acc2[p], pk2(s0, s1));
            }
        }
        __syncthreads();           // stage buffer free for reuse
    }

    // collapse packed halves, warp reduce, cross-warp via shared
    float acc[NP];
#pragma unroll
    for (int p = 0; p < NP; ++p) {
        float lo, hi; up2(acc2[p], lo, hi);
        acc[p] = lo + hi;
#pragma unroll
        for (int off = 16; off > 0; off >>= 1)
            acc[p] += __shfl_down_sync(0xffffffffu, acc[p], off);
    }

    __shared__ float sh[TPB/32][NP];
    int warp = tid >> 5, lane = tid & 31;
    if (lane == 0) {
#pragma unroll
        for (int p = 0; p < NP; ++p) sh[warp][p] = acc[p];
    }
    __syncthreads();
    if (tid < NP) {
        int p = tid;
        float s = 0.0f;
#pragma unroll
        for (int wi = 0; wi < TPB/32; ++wi) s += sh[wi][p];
        g_partial[blk*NP + p] = s * s_c[p];
    }
}

// ---------------------------------------------------------------------------
// Final: 384 threads; 4-way split of the 64-partial sums (L2 resident).
// ---------------------------------------------------------------------------
__global__ void final_kernel(const float* __restrict__ tq,
                             const float* __restrict__ rq,
                             float* __restrict__ out)
{
    __shared__ float sh4[NP*BATCH][4];
    __shared__ float s_pcl[NP*BATCH];
    __shared__ float s_rot[NP*BATCH];
    int t = threadIdx.x;

    if (t < 4*NP*BATCH) {                 // 384 threads
        int g = t >> 2, k = t & 3;
        int p = g / BATCH, bb = g % BATCH;
        float s = 0.0f;
#pragma unroll
        for (int j = 0; j < BPB/4; ++j)   // 16 each
            s += __ldcg(&g_partial[((size_t)bb*BPB + k*(BPB/4) + j)*NP + p]);
        sh4[g][k] = s;
    }
    __syncthreads();

    if (t < NP*BATCH) {
        int p = t / BATCH, bb = t % BATCH;
        s_pcl[t] = (sh4[t][0] + sh4[t][1] + sh4[t][2] + sh4[t][3])
                   * (1.0f / (float)NPTS);
        float w, x, y, z;
        qrel(tq, rq, p, bb, w, x, y, z);
        s_rot[t] = 2.0f * atan2f(sqrtf(x*x + y*y + z*z), fabsf(w));
    }
    __syncthreads();

    if (t == 0) {
        float total = 0.0f, rl = 0.0f, pl = 0.0f;
#pragma unroll
        for (int p = 0; p < NP; ++p) {
            float pcl = 0.0f, rot = 0.0f;
#pragma unroll
            for (int bb = 0; bb < BATCH; ++bb) {
                pcl += s_pcl[p*BATCH + bb];
                rot += s_rot[p*BATCH + bb];
            }
            rot *= (1.0f / (float)BATCH);
            float pclB = pcl * (1.0f / (float)BATCH);
            float wgt = W_GAMMA[p];
            total += wgt * (0.5f * rot + 0.5f * pclB);
            rl    += wgt * rot;
            pl    += wgt * pclB;
        }
        out[0] = total; out[1] = rl; out[2] = pl;
    }
}

extern "C" void kernel_launch(void* const* d_in, const int* in_sizes, int n_in,
                              void* d_out, int out_size)
{
    (void)in_sizes; (void)n_in; (void)out_size;
    const float* pc = (const float*)d_in[0];   // point_clouds [B,4,N]
    // d_in[1] = target_transl (cancels analytically — unused)
    const float* tr = (const float*)d_in[2];   // target_rot [B,4]
    const float* rl = (const float*)d_in[3];   // rot_list [P,B,4]

    pc_kernel   <<<NBLOCKS, TPB>>>(pc, tr, rl);
    final_kernel<<<1, 384>>>(tr, rl, (float*)d_out);
}